// round 14
// baseline (speedup 1.0000x reference)
#include <cuda_runtime.h>
#include <cuda_bf16.h>
#include <cstdint>
#include <math.h>

// Problem constants
#define BB 8192
#define P3 24
#define E_PER 90
#define EDGE_DIM 16
#define NROWS 196608   // B * 24

// Output layout (float32 concat of the 4 reference outputs)
#define OFF_NODE 0
#define OFF_EI 50331648
#define EI_HALF 737280
#define OFF_EA 51806208
#define OFF_BV 63602688

// ---------------------------------------------------------------------------
// Pre-generated B fragments for mma.m16n8k16 (bf16).
// Index: [c (16-col group, 0..15)][ks (0..15)][lane (0..31)] -> uint4
// ---------------------------------------------------------------------------
__device__ __align__(16) uint4 g_Wfrag[16 * 16 * 32];   // 128 KB

__device__ __forceinline__ uint32_t smem_u32(const void* p) {
    uint32_t a;
    asm("{ .reg .u64 t; cvta.to.shared.u64 t, %1; cvt.u32.u64 %0, t; }"
        : "=r"(a) : "l"(p));
    return a;
}

#define LDSM_X4(r0, r1, r2, r3, addr) \
    asm volatile("ldmatrix.sync.aligned.m8n8.x4.shared.b16 {%0,%1,%2,%3}, [%4];" \
        : "=r"(r0), "=r"(r1), "=r"(r2), "=r"(r3) : "r"(addr))

__device__ __forceinline__ void mma16816(float* d, uint32_t a0, uint32_t a1,
                                         uint32_t a2, uint32_t a3,
                                         uint32_t b0, uint32_t b1) {
    asm volatile(
        "mma.sync.aligned.m16n8k16.row.col.f32.bf16.bf16.f32 "
        "{%0,%1,%2,%3}, {%4,%5,%6,%7}, {%8,%9}, {%0,%1,%2,%3};"
        : "+f"(d[0]), "+f"(d[1]), "+f"(d[2]), "+f"(d[3])
        : "r"(a0), "r"(a1), "r"(a2), "r"(a3), "r"(b0), "r"(b1));
}

// ---------------------------------------------------------------------------
// prep: build g_Wfrag from Wq/Wk (f32)
// ---------------------------------------------------------------------------
__device__ __forceinline__ uint32_t pack_w(const float* __restrict__ Wq,
                                           const float* __restrict__ Wk,
                                           int n, int k) {
    const float* Wr = (n < 128) ? (Wq + (size_t)n * 256)
                                : (Wk + (size_t)(n - 128) * 256);
    __nv_bfloat162 h = __float22bfloat162_rn(make_float2(Wr[k], Wr[k + 1]));
    return *reinterpret_cast<uint32_t*>(&h);
}

__global__ void __launch_bounds__(256)
prep_kernel(const float* __restrict__ Wq, const float* __restrict__ Wk)
{
    int idx = blockIdx.x * 256 + threadIdx.x;     // 0..8191
    int c = idx >> 9, ks = (idx >> 5) & 15, l = idx & 31;
    int n0 = c * 16 + (l >> 2);
    int k0 = ks * 16 + (l & 3) * 2;
    uint4 u;
    u.x = pack_w(Wq, Wk, n0,     k0);
    u.y = pack_w(Wq, Wk, n0,     k0 + 8);
    u.z = pack_w(Wq, Wk, n0 + 8, k0);
    u.w = pack_w(Wq, Wk, n0 + 8, k0 + 8);
    g_Wfrag[idx] = u;
}

// ---------------------------------------------------------------------------
// fused kernel: 2 samples (48 rows) per block, 256 threads, 4 CTAs/SM.
// A tile loaded in 2 column-halves: half1 before MMA, half2 LDGs issued in
// batches INTERLEAVED with MMA ks0-7 (k-split software pipeline).
// Warps 0-3: q cols [32w,32w+32), m-tiles at row bases {0,24} (q rows).
// Warps 4-7: k cols,              m-tiles at row bases {8,32} (k rows).
// Y OVERLAYS A. smem: bias(1024) | pad | A/Y 48x512B swz (24576)
// ---------------------------------------------------------------------------
#define FS_BIAS 0
#define FS_A    2048
#define FS_Y    2048                // overlay (A dead after k-loop + barrier)
#define FS_TOTAL (2048 + 24576)     // 26624

__global__ void __launch_bounds__(256, 4)
fused_kernel(const float4* __restrict__ text, const float4* __restrict__ audio,
             const float4* __restrict__ facial,
             const float* __restrict__ bq, const float* __restrict__ bk,
             const float* __restrict__ emb, float* __restrict__ out)
{
    extern __shared__ char smc[];
    float* bias_s = (float*)(smc + FS_BIAS);

    const int t = threadIdx.x;
    const int l = t & 31;
    const int w = t >> 5;              // 0..7
    const int s0 = blockIdx.x * 2;     // first sample
    const int m0 = blockIdx.x * 48;    // first global row

    bias_s[t] = (t < 128) ? bq[t] : bk[t - 128];

    float4* out4 = (float4*)(out + OFF_NODE);

    // ---- A half1 (cols 0..127): load + node_feats copy + swizzled STS ----
#pragma unroll
    for (int it = 0; it < 6; ++it) {
        int idx = it * 256 + t;              // 0..1535
        int r = idx >> 5, c4 = idx & 31;
        int sl = (r >= 24), node = r - sl * 24;
        const float4* src = (node < 8) ? text : ((node < 16) ? audio : facial);
        float4 v = src[((size_t)(s0 + sl) * 8 + (node & 7)) * 64 + c4];
        out4[(size_t)(m0 + r) * 64 + c4] = v;
        __nv_bfloat162 h0 = __float22bfloat162_rn(make_float2(v.x, v.y));
        __nv_bfloat162 h1 = __float22bfloat162_rn(make_float2(v.z, v.w));
        uint2 u;
        u.x = *reinterpret_cast<uint32_t*>(&h0);
        u.y = *reinterpret_cast<uint32_t*>(&h1);
        int off = (r * 512 + c4 * 8) ^ ((r & 7) << 4);
        *reinterpret_cast<uint2*>(smc + FS_A + off) = u;
    }

    // ---- independent outputs (overlap LDG latency) ----
    // temporal attrs, vectorized: 2 samples * 168 float4
    {
        const float4* emb4 = (const float4*)emb;
        for (int o = t; o < 336; o += 256) {
            int sl = (o >= 168), rem = o - sl * 168;
            int e = rem >> 2, quad = rem & 3;
            int m = e / 14;
            float4 v4;
            if (quad < 2)       v4 = emb4[m * 2 + quad];
            else if (quad == 2) v4 = make_float4(0.0f, 0.125f, 1.0f, m * 0.25f);
            else                v4 = make_float4(0.0f, 0.0f, 0.0f, 0.0f);
            ((float4*)(out + OFF_EA))[(size_t)((s0 + sl) * E_PER + e) * 4 + quad] = v4;
        }
    }
    if (t < 180) {                               // edge_index: 2 * 90
        int sl = t / 90, e = t - sl * 90;
        int src, dst;
        if (e < 42) {
            int m = e / 14, r = e % 14, i = r >> 1, d = r & 1;
            int u_ = m * 8 + i, v_ = u_ + 1;
            src = d ? v_ : u_;
            dst = d ? u_ : v_;
        } else {
            int e2 = e - 42;
            int P = e2 >> 4, r = e2 & 15, i = r >> 1, d = r & 1;
            int oa = (P == 2) ? 8 : 0;
            int ob = (P == 0) ? 8 : 16;
            int a_ = oa + i, b_ = ob + i;
            src = d ? b_ : a_;
            dst = d ? a_ : b_;
        }
        int b = s0 + sl;
        out[OFF_EI + b * E_PER + e]           = (float)(src + b * P3);
        out[OFF_EI + EI_HALF + b * E_PER + e] = (float)(dst + b * P3);
    }
    if (t >= 192 && t < 240)                     // batch_vec: 48
        out[OFF_BV + m0 + (t - 192)] = (float)(s0 + (t - 192) / 24);

    __syncthreads();   // A half1 ready

    // ---- MMA setup ----
    const int rb0 = (w < 4) ? 0 : 8;
    const int rb1 = rb0 + 24;
    const int SX = (l & 7) << 4;
    const uint32_t As_u = smem_u32(smc + FS_A);
    const uint32_t a0_base = As_u + (uint32_t)((rb0 + (l & 15)) * 512 + (l >> 4) * 16);
    const uint32_t a1_base = As_u + (uint32_t)((rb1 + (l & 15)) * 512 + (l >> 4) * 16);
    const int g_ = l >> 2;
    const int tig = l & 3;
    const int SY = g_ << 4;
    const uint4* bp0 = g_Wfrag + ((w * 2) * 16) * 32 + l;

    float acc[2][4][4];
#pragma unroll
    for (int mt = 0; mt < 2; ++mt)
#pragma unroll
        for (int nt = 0; nt < 4; ++nt)
#pragma unroll
            for (int j = 0; j < 4; ++j) acc[mt][nt][j] = 0.0f;

#define MMA_KS_RANGE(KS0, KS1)                                              \
    _Pragma("unroll")                                                       \
    for (int ks = (KS0); ks < (KS1); ++ks) {                                \
        const uint32_t d0 = (uint32_t)(ks * 32);                            \
        uint4 bf0 = __ldg(bp0 + ks * 32);                                   \
        uint4 bf1 = __ldg(bp0 + ks * 32 + 512);                             \
        _Pragma("unroll")                                                   \
        for (int mt = 0; mt < 2; ++mt) {                                    \
            uint32_t a0, a1, a2, a3;                                        \
            uint32_t base = mt ? a1_base : a0_base;                         \
            LDSM_X4(a0, a1, a2, a3, (base + d0) ^ (uint32_t)SX);            \
            mma16816(acc[mt][0], a0, a1, a2, a3, bf0.x, bf0.y);             \
            mma16816(acc[mt][1], a0, a1, a2, a3, bf0.z, bf0.w);             \
            mma16816(acc[mt][2], a0, a1, a2, a3, bf1.x, bf1.y);             \
            mma16816(acc[mt][3], a0, a1, a2, a3, bf1.z, bf1.w);             \
        }                                                                   \
    }

#define LOAD_HALF2_BATCH(buf, IT0)                                          \
    _Pragma("unroll")                                                       \
    for (int b = 0; b < 3; ++b) {                                           \
        int idx = (IT0 + b) * 256 + t;                                      \
        int r = idx >> 5;                                                   \
        int c4 = 32 + (idx & 31);                                           \
        int sl = (r >= 24), node = r - sl * 24;                             \
        const float4* src = (node < 8) ? text                               \
                          : ((node < 16) ? audio : facial);                 \
        buf[b] = src[((size_t)(s0 + sl) * 8 + (node & 7)) * 64 + c4];       \
    }

#define STORE_HALF2_BATCH(buf, IT0)                                         \
    _Pragma("unroll")                                                       \
    for (int b = 0; b < 3; ++b) {                                           \
        int idx = (IT0 + b) * 256 + t;                                      \
        int r = idx >> 5;                                                   \
        int c4 = 32 + (idx & 31);                                           \
        float4 v = buf[b];                                                  \
        out4[(size_t)(m0 + r) * 64 + c4] = v;                               \
        __nv_bfloat162 h0 = __float22bfloat162_rn(make_float2(v.x, v.y));   \
        __nv_bfloat162 h1 = __float22bfloat162_rn(make_float2(v.z, v.w));   \
        uint2 u;                                                            \
        u.x = *reinterpret_cast<uint32_t*>(&h0);                            \
        u.y = *reinterpret_cast<uint32_t*>(&h1);                            \
        int off = (r * 512 + c4 * 8) ^ ((r & 7) << 4);                      \
        *reinterpret_cast<uint2*>(smc + FS_A + off) = u;                    \
    }

    // ---- pipelined: half2 LDGs interleaved with MMA on half1 ----
    {
        float4 buf[3];
        LOAD_HALF2_BATCH(buf, 0)
        MMA_KS_RANGE(0, 4)
        STORE_HALF2_BATCH(buf, 0)
        LOAD_HALF2_BATCH(buf, 3)
        MMA_KS_RANGE(4, 8)
        STORE_HALF2_BATCH(buf, 3)
    }
    __syncthreads();   // A half2 ready

    MMA_KS_RANGE(8, 16)

    __syncthreads();   // all warps done reading A before Y overlay

    // ---- bias + bf16 pack -> Y smem (overlays A) ----
#pragma unroll
    for (int mt = 0; mt < 2; ++mt) {
        int mrow = (mt ? rb1 : rb0) + g_;
#pragma unroll
        for (int nt = 0; nt < 4; ++nt) {
            int gc = w * 32 + nt * 8 + tig * 2;          // global col 0..255
            float b0 = bias_s[gc], b1 = bias_s[gc + 1];
            __nv_bfloat162 h0 = __float22bfloat162_rn(
                make_float2(acc[mt][nt][0] + b0, acc[mt][nt][1] + b1));
            __nv_bfloat162 h1 = __float22bfloat162_rn(
                make_float2(acc[mt][nt][2] + b0, acc[mt][nt][3] + b1));
            *reinterpret_cast<uint32_t*>(
                smc + FS_Y + ((mrow * 512 + gc * 2) ^ SY)) =
                *reinterpret_cast<uint32_t*>(&h0);
            *reinterpret_cast<uint32_t*>(
                smc + FS_Y + (((mrow + 8) * 512 + gc * 2) ^ SY)) =
                *reinterpret_cast<uint32_t*>(&h1);
        }
    }
    __syncthreads();   // Y ready

    // ---- dots + cross attrs: 2 pairs per iter, 16 lanes per pair ----
    const int h = l & 15;            // lane within pair group
#pragma unroll
    for (int j = 0; j < 3; ++j) {
        int d = w * 6 + j * 2 + (l >> 4);     // pair index 0..47
        int sl = (d >= 24), p = d - sl * 24;
        int P = p >> 3, i = p & 7;
        int qrow = sl * 24 + ((P < 2) ? i : (8 + i));
        int krow = sl * 24 + ((P == 0) ? (8 + i) : (16 + i));
        uint4 qu = *reinterpret_cast<const uint4*>(
            smc + FS_Y + ((qrow * 512 + h * 16) ^ ((qrow & 7) << 4)));
        uint4 ku = *reinterpret_cast<const uint4*>(
            smc + FS_Y + ((krow * 512 + 256 + h * 16) ^ ((krow & 7) << 4)));
        float2 q0 = __bfloat1622float2(*reinterpret_cast<__nv_bfloat162*>(&qu.x));
        float2 q1 = __bfloat1622float2(*reinterpret_cast<__nv_bfloat162*>(&qu.y));
        float2 q2 = __bfloat1622float2(*reinterpret_cast<__nv_bfloat162*>(&qu.z));
        float2 q3 = __bfloat1622float2(*reinterpret_cast<__nv_bfloat162*>(&qu.w));
        float2 k0 = __bfloat1622float2(*reinterpret_cast<__nv_bfloat162*>(&ku.x));
        float2 k1 = __bfloat1622float2(*reinterpret_cast<__nv_bfloat162*>(&ku.y));
        float2 k2 = __bfloat1622float2(*reinterpret_cast<__nv_bfloat162*>(&ku.z));
        float2 k3 = __bfloat1622float2(*reinterpret_cast<__nv_bfloat162*>(&ku.w));
        float sqk = q0.x*k0.x + q0.y*k0.y + q1.x*k1.x + q1.y*k1.y
                  + q2.x*k2.x + q2.y*k2.y + q3.x*k3.x + q3.y*k3.y;
        float sqq = q0.x*q0.x + q0.y*q0.y + q1.x*q1.x + q1.y*q1.y
                  + q2.x*q2.x + q2.y*q2.y + q3.x*q3.x + q3.y*q3.y;
        float skk = k0.x*k0.x + k0.y*k0.y + k1.x*k1.x + k1.y*k1.y
                  + k2.x*k2.x + k2.y*k2.y + k3.x*k3.x + k3.y*k3.y;
#pragma unroll
        for (int off = 8; off > 0; off >>= 1) {
            sqk += __shfl_xor_sync(0xffffffffu, sqk, off);
            sqq += __shfl_xor_sync(0xffffffffu, sqq, off);
            skk += __shfl_xor_sync(0xffffffffu, skk, off);
        }
        float dv = sqk * rsqrtf(fmaxf(sqq, 1e-24f)) * rsqrtf(fmaxf(skk, 1e-24f));
        float disc = 1.0f / (1.0f + expf(dv));
        int et = (disc > 0.4f) ? 4 : 3;
        float v;
        if (h < 8)        v = emb[et * 8 + h];
        else if (h == 8)  v = disc;
        else if (h == 11) v = et * 0.25f;
        else              v = 0.0f;
        float* base = out + OFF_EA
            + (size_t)((s0 + sl) * E_PER + 42 + 2 * p) * EDGE_DIM;
        base[h]      = v;
        base[h + 16] = v;
    }
}

// ---------------------------------------------------------------------------
extern "C" void kernel_launch(void* const* d_in, const int* in_sizes, int n_in,
                              void* d_out, int out_size)
{
    const float* z_text   = (const float*)d_in[0];
    const float* z_audio  = (const float*)d_in[1];
    const float* z_facial = (const float*)d_in[2];
    const float* Wq       = (const float*)d_in[3];
    const float* bq       = (const float*)d_in[4];
    const float* Wk       = (const float*)d_in[5];
    const float* bk       = (const float*)d_in[6];
    const float* emb      = (const float*)d_in[7];
    float* out = (float*)d_out;

    cudaFuncSetAttribute(fused_kernel, cudaFuncAttributeMaxDynamicSharedMemorySize,
                         FS_TOTAL);

    prep_kernel<<<32, 256>>>(Wq, Wk);

    fused_kernel<<<NROWS / 48, 256, FS_TOTAL>>>(
        (const float4*)z_text, (const float4*)z_audio, (const float4*)z_facial,
        bq, bk, emb, out);
}

// round 15
// speedup vs baseline: 1.5960x; 1.5960x over previous
#include <cuda_runtime.h>
#include <cuda_bf16.h>
#include <cstdint>
#include <math.h>

// Problem constants
#define BB 8192
#define P3 24
#define E_PER 90
#define EDGE_DIM 16
#define NROWS 196608   // B * 24

// Output layout (float32 concat of the 4 reference outputs)
#define OFF_NODE 0
#define OFF_EI 50331648
#define EI_HALF 737280
#define OFF_EA 51806208
#define OFF_BV 63602688

// ---------------------------------------------------------------------------
// Pre-generated B fragments for mma.m16n8k16 (bf16).
// Index: [c (16-col group, 0..15)][ks (0..15)][lane (0..31)] -> uint4
// ---------------------------------------------------------------------------
__device__ __align__(16) uint4 g_Wfrag[16 * 16 * 32];   // 128 KB

__device__ __forceinline__ uint32_t smem_u32(const void* p) {
    uint32_t a;
    asm("{ .reg .u64 t; cvta.to.shared.u64 t, %1; cvt.u32.u64 %0, t; }"
        : "=r"(a) : "l"(p));
    return a;
}

__device__ __forceinline__ void stcs4(float4* p, float4 v) {
    asm volatile("st.global.cs.v4.f32 [%0], {%1,%2,%3,%4};"
                 :: "l"(p), "f"(v.x), "f"(v.y), "f"(v.z), "f"(v.w) : "memory");
}

#define LDSM_X4(r0, r1, r2, r3, addr) \
    asm volatile("ldmatrix.sync.aligned.m8n8.x4.shared.b16 {%0,%1,%2,%3}, [%4];" \
        : "=r"(r0), "=r"(r1), "=r"(r2), "=r"(r3) : "r"(addr))

__device__ __forceinline__ void mma16816(float* d, uint32_t a0, uint32_t a1,
                                         uint32_t a2, uint32_t a3,
                                         uint32_t b0, uint32_t b1) {
    asm volatile(
        "mma.sync.aligned.m16n8k16.row.col.f32.bf16.bf16.f32 "
        "{%0,%1,%2,%3}, {%4,%5,%6,%7}, {%8,%9}, {%0,%1,%2,%3};"
        : "+f"(d[0]), "+f"(d[1]), "+f"(d[2]), "+f"(d[3])
        : "r"(a0), "r"(a1), "r"(a2), "r"(a3), "r"(b0), "r"(b1));
}

// ---------------------------------------------------------------------------
// prep: build g_Wfrag from Wq/Wk (f32)
// ---------------------------------------------------------------------------
__device__ __forceinline__ uint32_t pack_w(const float* __restrict__ Wq,
                                           const float* __restrict__ Wk,
                                           int n, int k) {
    const float* Wr = (n < 128) ? (Wq + (size_t)n * 256)
                                : (Wk + (size_t)(n - 128) * 256);
    __nv_bfloat162 h = __float22bfloat162_rn(make_float2(Wr[k], Wr[k + 1]));
    return *reinterpret_cast<uint32_t*>(&h);
}

__global__ void __launch_bounds__(256)
prep_kernel(const float* __restrict__ Wq, const float* __restrict__ Wk)
{
    int idx = blockIdx.x * 256 + threadIdx.x;     // 0..8191
    int c = idx >> 9, ks = (idx >> 5) & 15, l = idx & 31;
    int n0 = c * 16 + (l >> 2);
    int k0 = ks * 16 + (l & 3) * 2;
    uint4 u;
    u.x = pack_w(Wq, Wk, n0,     k0);
    u.y = pack_w(Wq, Wk, n0,     k0 + 8);
    u.z = pack_w(Wq, Wk, n0 + 8, k0);
    u.w = pack_w(Wq, Wk, n0 + 8, k0 + 8);
    g_Wfrag[idx] = u;
}

// ---------------------------------------------------------------------------
// fused kernel: 2 samples (48 rows) per block, 256 threads, 4 CTAs/SM.
// Warps 0-3: q cols [32w,32w+32), m-tiles at row bases {0,24} (q rows).
// Warps 4-7: k cols,              m-tiles at row bases {8,32} (k rows).
// Y OVERLAYS A (smem 26.6KB/CTA -> per-SM smem 106.5KB -> L1D ~121KB, so
// the 128KB Wfrag stream stays L1-resident across the 4 co-located CTAs).
// smem: bias(1024) | pad | A/Y 48x512B swz (24576)
// ---------------------------------------------------------------------------
#define FS_BIAS 0
#define FS_A    2048
#define FS_Y    2048                // overlay (A dead after k-loop + barrier)
#define FS_TOTAL (2048 + 24576)     // 26624

__global__ void __launch_bounds__(256, 4)
fused_kernel(const float4* __restrict__ text, const float4* __restrict__ audio,
             const float4* __restrict__ facial,
             const float* __restrict__ bq, const float* __restrict__ bk,
             const float* __restrict__ emb, float* __restrict__ out)
{
    extern __shared__ char smc[];
    float* bias_s = (float*)(smc + FS_BIAS);

    const int t = threadIdx.x;
    const int l = t & 31;
    const int w = t >> 5;              // 0..7
    const int s0 = blockIdx.x * 2;     // first sample
    const int m0 = blockIdx.x * 48;    // first global row

    bias_s[t] = (t < 128) ? bq[t] : bk[t - 128];

    // ---- A tile load (bf16, swizzled) + fused node_feats copy ----
    float4* out4 = (float4*)(out + OFF_NODE);
#pragma unroll
    for (int it = 0; it < 12; ++it) {
        int idx = it * 256 + t;              // 0..3071
        int r = idx >> 6, c4 = idx & 63;
        int sl = (r >= 24), node = r - sl * 24;
        const float4* src = (node < 8) ? text : ((node < 16) ? audio : facial);
        float4 v = src[((size_t)(s0 + sl) * 8 + (node & 7)) * 64 + c4];
        stcs4(out4 + (size_t)(m0 + r) * 64 + c4, v);
        __nv_bfloat162 h0 = __float22bfloat162_rn(make_float2(v.x, v.y));
        __nv_bfloat162 h1 = __float22bfloat162_rn(make_float2(v.z, v.w));
        uint2 u;
        u.x = *reinterpret_cast<uint32_t*>(&h0);
        u.y = *reinterpret_cast<uint32_t*>(&h1);
        int off = (r * 512 + c4 * 8) ^ ((r & 7) << 4);
        *reinterpret_cast<uint2*>(smc + FS_A + off) = u;
    }

    // ---- independent outputs (overlap other CTAs' MMA) ----
    {   // temporal attrs, vectorized: 2 samples * 42 edges * 4 float4
        const float4* emb4 = (const float4*)emb;
        for (int o = t; o < 336; o += 256) {
            int sl = (o >= 168), rem = o - sl * 168;
            int e = rem >> 2, quad = rem & 3;
            int m = e / 14;
            float4 v4;
            if (quad < 2)       v4 = emb4[m * 2 + quad];
            else if (quad == 2) v4 = make_float4(0.0f, 0.125f, 1.0f, m * 0.25f);
            else                v4 = make_float4(0.0f, 0.0f, 0.0f, 0.0f);
            ((float4*)(out + OFF_EA))[(size_t)((s0 + sl) * E_PER + e) * 4 + quad] = v4;
        }
    }
    if (t < 180) {                               // edge_index: 2 * 90
        int sl = t / 90, e = t - sl * 90;
        int src, dst;
        if (e < 42) {
            int m = e / 14, r = e % 14, i = r >> 1, d = r & 1;
            int u_ = m * 8 + i, v_ = u_ + 1;
            src = d ? v_ : u_;
            dst = d ? u_ : v_;
        } else {
            int e2 = e - 42;
            int P = e2 >> 4, r = e2 & 15, i = r >> 1, d = r & 1;
            int oa = (P == 2) ? 8 : 0;
            int ob = (P == 0) ? 8 : 16;
            int a_ = oa + i, b_ = ob + i;
            src = d ? b_ : a_;
            dst = d ? a_ : b_;
        }
        int b = s0 + sl;
        out[OFF_EI + b * E_PER + e]           = (float)(src + b * P3);
        out[OFF_EI + EI_HALF + b * E_PER + e] = (float)(dst + b * P3);
    }
    if (t >= 192 && t < 240)                     // batch_vec: 48
        out[OFF_BV + m0 + (t - 192)] = (float)(s0 + (t - 192) / 24);

    __syncthreads();   // A tile ready

    // ---- HMMA single pass, needed rows only ----
    const int rb0 = (w < 4) ? 0 : 8;
    const int rb1 = rb0 + 24;

    const int SX = (l & 7) << 4;
    const uint32_t As_u = smem_u32(smc + FS_A);
    const uint32_t a0_base = As_u + (uint32_t)((rb0 + (l & 15)) * 512 + (l >> 4) * 16);
    const uint32_t a1_base = As_u + (uint32_t)((rb1 + (l & 15)) * 512 + (l >> 4) * 16);

    const int g_ = l >> 2;
    const int tig = l & 3;
    const int SY = g_ << 4;

    const uint4* bp0 = g_Wfrag + ((w * 2) * 16) * 32 + l;

    float acc[2][4][4];
#pragma unroll
    for (int mt = 0; mt < 2; ++mt)
#pragma unroll
        for (int nt = 0; nt < 4; ++nt)
#pragma unroll
            for (int j = 0; j < 4; ++j) acc[mt][nt][j] = 0.0f;

#pragma unroll
    for (int ks = 0; ks < 16; ++ks) {
        const uint32_t d0 = (uint32_t)(ks * 32);
        uint4 bf0 = __ldg(bp0 + ks * 32);
        uint4 bf1 = __ldg(bp0 + ks * 32 + 512);
#pragma unroll
        for (int mt = 0; mt < 2; ++mt) {
            uint32_t a0, a1, a2, a3;
            uint32_t base = mt ? a1_base : a0_base;
            LDSM_X4(a0, a1, a2, a3, (base + d0) ^ (uint32_t)SX);
            mma16816(acc[mt][0], a0, a1, a2, a3, bf0.x, bf0.y);
            mma16816(acc[mt][1], a0, a1, a2, a3, bf0.z, bf0.w);
            mma16816(acc[mt][2], a0, a1, a2, a3, bf1.x, bf1.y);
            mma16816(acc[mt][3], a0, a1, a2, a3, bf1.z, bf1.w);
        }
    }

    __syncthreads();   // all warps done reading A before Y overlay

    // ---- bias + bf16 pack -> Y smem (overlays A) ----
#pragma unroll
    for (int mt = 0; mt < 2; ++mt) {
        int mrow = (mt ? rb1 : rb0) + g_;
#pragma unroll
        for (int nt = 0; nt < 4; ++nt) {
            int gc = w * 32 + nt * 8 + tig * 2;          // global col 0..255
            float b0 = bias_s[gc], b1 = bias_s[gc + 1];
            __nv_bfloat162 h0 = __float22bfloat162_rn(
                make_float2(acc[mt][nt][0] + b0, acc[mt][nt][1] + b1));
            __nv_bfloat162 h1 = __float22bfloat162_rn(
                make_float2(acc[mt][nt][2] + b0, acc[mt][nt][3] + b1));
            *reinterpret_cast<uint32_t*>(
                smc + FS_Y + ((mrow * 512 + gc * 2) ^ SY)) =
                *reinterpret_cast<uint32_t*>(&h0);
            *reinterpret_cast<uint32_t*>(
                smc + FS_Y + (((mrow + 8) * 512 + gc * 2) ^ SY)) =
                *reinterpret_cast<uint32_t*>(&h1);
        }
    }
    __syncthreads();   // Y ready

    // ---- dots + cross attrs: 2 pairs per iter, 16 lanes per pair ----
    const int h = l & 15;            // lane within pair group
#pragma unroll
    for (int j = 0; j < 3; ++j) {
        int d = w * 6 + j * 2 + (l >> 4);     // pair index 0..47
        int sl = (d >= 24), p = d - sl * 24;
        int P = p >> 3, i = p & 7;
        int qrow = sl * 24 + ((P < 2) ? i : (8 + i));
        int krow = sl * 24 + ((P == 0) ? (8 + i) : (16 + i));
        uint4 qu = *reinterpret_cast<const uint4*>(
            smc + FS_Y + ((qrow * 512 + h * 16) ^ ((qrow & 7) << 4)));
        uint4 ku = *reinterpret_cast<const uint4*>(
            smc + FS_Y + ((krow * 512 + 256 + h * 16) ^ ((krow & 7) << 4)));
        float2 q0 = __bfloat1622float2(*reinterpret_cast<__nv_bfloat162*>(&qu.x));
        float2 q1 = __bfloat1622float2(*reinterpret_cast<__nv_bfloat162*>(&qu.y));
        float2 q2 = __bfloat1622float2(*reinterpret_cast<__nv_bfloat162*>(&qu.z));
        float2 q3 = __bfloat1622float2(*reinterpret_cast<__nv_bfloat162*>(&qu.w));
        float2 k0 = __bfloat1622float2(*reinterpret_cast<__nv_bfloat162*>(&ku.x));
        float2 k1 = __bfloat1622float2(*reinterpret_cast<__nv_bfloat162*>(&ku.y));
        float2 k2 = __bfloat1622float2(*reinterpret_cast<__nv_bfloat162*>(&ku.z));
        float2 k3 = __bfloat1622float2(*reinterpret_cast<__nv_bfloat162*>(&ku.w));
        float sqk = q0.x*k0.x + q0.y*k0.y + q1.x*k1.x + q1.y*k1.y
                  + q2.x*k2.x + q2.y*k2.y + q3.x*k3.x + q3.y*k3.y;
        float sqq = q0.x*q0.x + q0.y*q0.y + q1.x*q1.x + q1.y*q1.y
                  + q2.x*q2.x + q2.y*q2.y + q3.x*q3.x + q3.y*q3.y;
        float skk = k0.x*k0.x + k0.y*k0.y + k1.x*k1.x + k1.y*k1.y
                  + k2.x*k2.x + k2.y*k2.y + k3.x*k3.x + k3.y*k3.y;
#pragma unroll
        for (int off = 8; off > 0; off >>= 1) {
            sqk += __shfl_xor_sync(0xffffffffu, sqk, off);
            sqq += __shfl_xor_sync(0xffffffffu, sqq, off);
            skk += __shfl_xor_sync(0xffffffffu, skk, off);
        }
        float dv = sqk * rsqrtf(fmaxf(sqq, 1e-24f)) * rsqrtf(fmaxf(skk, 1e-24f));
        float disc = 1.0f / (1.0f + __expf(dv));
        int et = (disc > 0.4f) ? 4 : 3;
        float v;
        if (h < 8)        v = emb[et * 8 + h];
        else if (h == 8)  v = disc;
        else if (h == 11) v = et * 0.25f;
        else              v = 0.0f;
        float* base = out + OFF_EA
            + (size_t)((s0 + sl) * E_PER + 42 + 2 * p) * EDGE_DIM;
        base[h]      = v;
        base[h + 16] = v;
    }
}

// ---------------------------------------------------------------------------
extern "C" void kernel_launch(void* const* d_in, const int* in_sizes, int n_in,
                              void* d_out, int out_size)
{
    const float* z_text   = (const float*)d_in[0];
    const float* z_audio  = (const float*)d_in[1];
    const float* z_facial = (const float*)d_in[2];
    const float* Wq       = (const float*)d_in[3];
    const float* bq       = (const float*)d_in[4];
    const float* Wk       = (const float*)d_in[5];
    const float* bk       = (const float*)d_in[6];
    const float* emb      = (const float*)d_in[7];
    float* out = (float*)d_out;

    cudaFuncSetAttribute(fused_kernel, cudaFuncAttributeMaxDynamicSharedMemorySize,
                         FS_TOTAL);

    prep_kernel<<<32, 256>>>(Wq, Wk);

    fused_kernel<<<NROWS / 48, 256, FS_TOTAL>>>(
        (const float4*)z_text, (const float4*)z_audio, (const float4*)z_facial,
        bq, bk, emb, out);
}